// round 3
// baseline (speedup 1.0000x reference)
#include <cuda_runtime.h>
#include <cuda_bf16.h>
#include <stdint.h>

#define N_TOK_TOTAL 16384
#define DPROJ 1024
#define EMB_SCALE 32.0f

// device scratch (no allocations allowed)
__device__ int g_count[4];
__device__ int g_list[4][N_TOK_TOTAL];   // flat token index (output row)
__device__ int g_row[4][N_TOK_TOTAL];    // local embedding row

__global__ void reset_kernel() {
    if (threadIdx.x < 4) g_count[threadIdx.x] = 0;
}

__global__ void partition_kernel(const int* __restrict__ inp) {
    int t = blockIdx.x * blockDim.x + threadIdx.x;
    if (t >= N_TOK_TOTAL) return;
    int idx = inp[t];
    int c, l;
    if (idx < 20000)      { c = 0; l = 0; }
    else if (idx < 40000) { c = 1; l = 20000; }
    else if (idx < 200000){ c = 2; l = 40000; }
    else                  { c = 3; l = 200000; }
    int pos = atomicAdd(&g_count[c], 1);
    g_list[c][pos] = t;
    g_row[c][pos]  = idx - l;
}

// Tiled fp32 GEMM per cluster:
//   C[tok, p] = scale * sum_k emb[row_tok, k] * proj[p, k]
// Block tile: TM=128 tokens x TN=64 proj cols, BK k-slab.
// 256 threads, 8x4 register micro-tile per thread.
template<int D, int BK, int CLUSTER>
__global__ __launch_bounds__(256, 2)
void gemm_kernel(const float* __restrict__ emb,
                 const float* __restrict__ proj,
                 float* __restrict__ out) {
    constexpr int TM = 128, TN = 64;
    constexpr int SA_STRIDE = TM + 4;   // 132 floats: rows stay 16B-aligned
    constexpr int SB_STRIDE = TN + 4;   // 68 floats
    __shared__ float sA[BK][SA_STRIDE];
    __shared__ float sB[BK][SB_STRIDE];

    const int count = g_count[CLUSTER];
    const int m0 = blockIdx.x * TM;
    if (m0 >= count) return;
    const int n0 = blockIdx.y * TN;

    const int tid = threadIdx.x;
    const int tx = tid & 15;          // col group (4 cols)
    const int ty = tid >> 4;          // token group (8 tokens)

    // Per-thread A-load assignment: TM*BK/4 float4 slots over 256 threads
    constexpr int KQ = BK / 4;                    // float4 per row
    constexpr int A_LD = (TM * KQ) / 256;         // BK=32 -> 4, BK=16 -> 2
    constexpr int B_LD = (TN * KQ) / 256;         // BK=32 -> 2, BK=16 -> 1

    // precompute gathered emb row per A-load slot (valid for all k slabs)
    int arow[A_LD];
#pragma unroll
    for (int j = 0; j < A_LD; j++) {
        int slot = tid + j * 256;
        int m = slot / KQ;
        arow[j] = (m0 + m < count) ? g_row[CLUSTER][m0 + m] : -1;
    }

    float acc[8][4];
#pragma unroll
    for (int i = 0; i < 8; i++)
#pragma unroll
        for (int j = 0; j < 4; j++) acc[i][j] = 0.0f;

    for (int k0 = 0; k0 < D; k0 += BK) {
        // ---- load A (gathered emb rows), store transposed sA[k][m]
#pragma unroll
        for (int j = 0; j < A_LD; j++) {
            int slot = tid + j * 256;
            int m  = slot / KQ;
            int kq = slot % KQ;
            float4 v = make_float4(0.f, 0.f, 0.f, 0.f);
            if (arow[j] >= 0)
                v = *(const float4*)(emb + (size_t)arow[j] * D + k0 + kq * 4);
            sA[kq * 4 + 0][m] = v.x;
            sA[kq * 4 + 1][m] = v.y;
            sA[kq * 4 + 2][m] = v.z;
            sA[kq * 4 + 3][m] = v.w;
        }
        // ---- load B (proj rows), store transposed sB[k][p]
#pragma unroll
        for (int j = 0; j < B_LD; j++) {
            int slot = tid + j * 256;
            int p  = slot / KQ;
            int kq = slot % KQ;
            float4 v = *(const float4*)(proj + (size_t)(n0 + p) * D + k0 + kq * 4);
            sB[kq * 4 + 0][p] = v.x;
            sB[kq * 4 + 1][p] = v.y;
            sB[kq * 4 + 2][p] = v.z;
            sB[kq * 4 + 3][p] = v.w;
        }
        __syncthreads();

#pragma unroll
        for (int kk = 0; kk < BK; kk++) {
            float a[8], b[4];
            float4 a0 = *(const float4*)&sA[kk][ty * 8];
            float4 a1 = *(const float4*)&sA[kk][ty * 8 + 4];
            a[0] = a0.x; a[1] = a0.y; a[2] = a0.z; a[3] = a0.w;
            a[4] = a1.x; a[5] = a1.y; a[6] = a1.z; a[7] = a1.w;
            float4 b0 = *(const float4*)&sB[kk][tx * 4];
            b[0] = b0.x; b[1] = b0.y; b[2] = b0.z; b[3] = b0.w;
#pragma unroll
            for (int i = 0; i < 8; i++)
#pragma unroll
                for (int j = 0; j < 4; j++)
                    acc[i][j] = fmaf(a[i], b[j], acc[i][j]);
        }
        __syncthreads();
    }

    // ---- write out (each token owned by exactly one cluster -> plain store)
#pragma unroll
    for (int i = 0; i < 8; i++) {
        int m = ty * 8 + i;
        if (m0 + m < count) {
            int tok = g_list[CLUSTER][m0 + m];
            float4 v = make_float4(acc[i][0] * EMB_SCALE, acc[i][1] * EMB_SCALE,
                                   acc[i][2] * EMB_SCALE, acc[i][3] * EMB_SCALE);
            *(float4*)(out + (size_t)tok * DPROJ + n0 + tx * 4) = v;
        }
    }
}

extern "C" void kernel_launch(void* const* d_in, const int* in_sizes, int n_in,
                              void* d_out, int out_size) {
    // Map inputs by element count (robust to metadata ordering).
    // Expected: inp=16384(int), emb0=20000*1024, proj0=1024*1024,
    //           emb1=20000*256, proj1=1024*256, emb2=160000*64, proj2=1024*64,
    //           emb3=67735*16, proj3=1024*16
    const int* inp = (const int*)d_in[0];
    const float *emb[4] = {0, 0, 0, 0}, *proj[4] = {0, 0, 0, 0};
    for (int i = 1; i < n_in; i++) {
        long sz = in_sizes[i];
        const float* p = (const float*)d_in[i];
        switch (sz) {
            case 20000L * 1024:  emb[0]  = p; break;
            case 1024L * 1024:   proj[0] = p; break;
            case 20000L * 256:   emb[1]  = p; break;
            case 1024L * 256:    proj[1] = p; break;
            case 160000L * 64:   emb[2]  = p; break;
            case 1024L * 64:     proj[2] = p; break;
            case 67735L * 16:    emb[3]  = p; break;
            case 1024L * 16:     proj[3] = p; break;
            default: break;
        }
    }
    float* out = (float*)d_out;

    reset_kernel<<<1, 32>>>();
    partition_kernel<<<N_TOK_TOTAL / 256, 256>>>(inp);

    dim3 grid(N_TOK_TOTAL / 128, DPROJ / 64);
    gemm_kernel<1024, 32, 0><<<grid, 256>>>(emb[0], proj[0], out);
    gemm_kernel< 256, 32, 1><<<grid, 256>>>(emb[1], proj[1], out);
    gemm_kernel<  64, 32, 2><<<grid, 256>>>(emb[2], proj[2], out);
    gemm_kernel<  16, 16, 3><<<grid, 256>>>(emb[3], proj[3], out);
}

// round 6
// speedup vs baseline: 2.6741x; 2.6741x over previous
#include <cuda_runtime.h>
#include <stdint.h>

#define N_TOK_TOTAL 16384
#define DPROJ 1024
#define EMB_SCALE 32.0f

// ---------------- device scratch (no allocations allowed) ----------------
__device__ int g_count[4];
__device__ int g_list[4][N_TOK_TOTAL];   // flat token index (output row)
__device__ int g_row[4][N_TOK_TOTAL];    // local embedding row

__global__ void reset_kernel() {
    if (threadIdx.x < 4) g_count[threadIdx.x] = 0;
}

__global__ void partition_kernel(const int* __restrict__ inp) {
    int t = blockIdx.x * blockDim.x + threadIdx.x;
    if (t >= N_TOK_TOTAL) return;
    int idx = inp[t];
    int c, l;
    if (idx < 20000)      { c = 0; l = 0; }
    else if (idx < 40000) { c = 1; l = 20000; }
    else if (idx < 200000){ c = 2; l = 40000; }
    else                  { c = 3; l = 200000; }
    int pos = atomicAdd(&g_count[c], 1);
    g_list[c][pos] = t;
    g_row[c][pos]  = idx - l;
}

__device__ __forceinline__ uint32_t f2tf32(float f) {
    uint32_t u;
    asm("cvt.rna.tf32.f32 %0, %1;" : "=r"(u) : "f"(f));
    return u;
}

// ---------------- fused tf32 mma.sync GEMM ----------------
// grid: (m-tile[128], n-tile[64], cluster). Early-exit on dynamic counts.
// D[m, n] = sum_k A[m, k] * B[n, k]; A = gathered emb rows, B = proj rows.
// 8 warps in 4(M) x 2(N) grid; each warp 32x32 via m16n8k8 tf32 frags.
__global__ __launch_bounds__(256)
void fused_gemm_tc(const float* __restrict__ e0, const float* __restrict__ e1,
                   const float* __restrict__ e2, const float* __restrict__ e3,
                   const float* __restrict__ p0, const float* __restrict__ p1,
                   const float* __restrict__ p2, const float* __restrict__ p3,
                   float* __restrict__ out)
{
    constexpr int TM = 128, TN = 64, BK = 32;
    constexpr int ST = 36;                     // padded stride (floats); 144B rows
    __shared__ float sA[TM * ST];              // 18.4 KB (holds tf32-rounded bits)
    __shared__ float sB[TN * ST];              // 9.2 KB

    const int c = blockIdx.z;
    const int count = g_count[c];
    const int m0 = blockIdx.x * TM;
    if (m0 >= count) return;
    const int n0 = blockIdx.y * TN;

    const float* emb  = (c == 0) ? e0 : (c == 1) ? e1 : (c == 2) ? e2 : e3;
    const float* proj = (c == 0) ? p0 : (c == 1) ? p1 : (c == 2) ? p2 : p3;
    const int K = (c == 0) ? 1024 : (c == 1) ? 256 : (c == 2) ? 64 : 16;

    const int tid = threadIdx.x;
    const int wid = tid >> 5;
    const int lid = tid & 31;
    const int wy = wid & 3;          // M warp coord (x32)
    const int wx = wid >> 2;         // N warp coord (x32)
    const int g   = lid >> 2;        // fragment groupID (0..7)
    const int tig = lid & 3;         // thread-in-group (0..3)

    // A-load slots: 128 rows x 8 float4 = 1024 over 256 threads -> 4 each
    int arow[4];
#pragma unroll
    for (int j = 0; j < 4; j++) {
        int slot = tid + j * 256;
        int m = slot >> 3;
        arow[j] = (m0 + m < count) ? g_row[c][m0 + m] : -1;
    }

    float acc[2][4][4];
#pragma unroll
    for (int mf = 0; mf < 2; mf++)
#pragma unroll
        for (int nf = 0; nf < 4; nf++)
#pragma unroll
            for (int q = 0; q < 4; q++) acc[mf][nf][q] = 0.0f;

    for (int k0 = 0; k0 < K; k0 += BK) {
        // ---- producer: gather A rows, round to tf32, store padded
#pragma unroll
        for (int j = 0; j < 4; j++) {
            int slot = tid + j * 256;
            int m = slot >> 3, kq = slot & 7;
            int kk = k0 + kq * 4;
            float4 v = make_float4(0.f, 0.f, 0.f, 0.f);
            if (arow[j] >= 0 && kk < K)
                v = *(const float4*)(emb + (size_t)arow[j] * K + kk);
            float* d = &sA[m * ST + kq * 4];
            d[0] = __uint_as_float(f2tf32(v.x));
            d[1] = __uint_as_float(f2tf32(v.y));
            d[2] = __uint_as_float(f2tf32(v.z));
            d[3] = __uint_as_float(f2tf32(v.w));
        }
        // ---- producer: B proj rows (64 x 8 float4 = 512 slots -> 2 each)
#pragma unroll
        for (int j = 0; j < 2; j++) {
            int slot = tid + j * 256;
            int n = slot >> 3, kq = slot & 7;
            int kk = k0 + kq * 4;
            float4 v = make_float4(0.f, 0.f, 0.f, 0.f);
            if (kk < K)
                v = *(const float4*)(proj + (size_t)(n0 + n) * K + kk);
            float* d = &sB[n * ST + kq * 4];
            d[0] = __uint_as_float(f2tf32(v.x));
            d[1] = __uint_as_float(f2tf32(v.y));
            d[2] = __uint_as_float(f2tf32(v.z));
            d[3] = __uint_as_float(f2tf32(v.w));
        }
        __syncthreads();

        // ---- consumer: 4 k-steps of m16n8k8
#pragma unroll
        for (int ks = 0; ks < 4; ks++) {
            const int kk = ks * 8;
            uint32_t A[2][4], B[4][2];
#pragma unroll
            for (int mf = 0; mf < 2; mf++) {
                const float* ba = &sA[(wy * 32 + mf * 16 + g) * ST + kk + tig];
                A[mf][0] = __float_as_uint(ba[0]);
                A[mf][1] = __float_as_uint(ba[8 * ST]);
                A[mf][2] = __float_as_uint(ba[4]);
                A[mf][3] = __float_as_uint(ba[8 * ST + 4]);
            }
#pragma unroll
            for (int nf = 0; nf < 4; nf++) {
                const float* bb = &sB[(wx * 32 + nf * 8 + g) * ST + kk + tig];
                B[nf][0] = __float_as_uint(bb[0]);
                B[nf][1] = __float_as_uint(bb[4]);
            }
#pragma unroll
            for (int mf = 0; mf < 2; mf++)
#pragma unroll
                for (int nf = 0; nf < 4; nf++) {
                    asm volatile(
                        "mma.sync.aligned.m16n8k8.row.col.f32.tf32.tf32.f32 "
                        "{%0,%1,%2,%3}, {%4,%5,%6,%7}, {%8,%9}, {%0,%1,%2,%3};"
                        : "+f"(acc[mf][nf][0]), "+f"(acc[mf][nf][1]),
                          "+f"(acc[mf][nf][2]), "+f"(acc[mf][nf][3])
                        : "r"(A[mf][0]), "r"(A[mf][1]), "r"(A[mf][2]), "r"(A[mf][3]),
                          "r"(B[nf][0]), "r"(B[nf][1]));
                }
        }
        __syncthreads();
    }

    // ---- epilogue: c0,c1 at (row g, col 2*tig..+1); c2,c3 at row g+8
#pragma unroll
    for (int mf = 0; mf < 2; mf++) {
        int r0 = m0 + wy * 32 + mf * 16 + g;
        int r1 = r0 + 8;
        bool v0 = r0 < count, v1 = r1 < count;
        float* o0 = v0 ? out + (size_t)g_list[c][r0] * DPROJ + n0 : nullptr;
        float* o1 = v1 ? out + (size_t)g_list[c][r1] * DPROJ + n0 : nullptr;
#pragma unroll
        for (int nf = 0; nf < 4; nf++) {
            int col = wx * 32 + nf * 8 + 2 * tig;
            if (v0) {
                float2 w = make_float2(acc[mf][nf][0] * EMB_SCALE,
                                       acc[mf][nf][1] * EMB_SCALE);
                *(float2*)(o0 + col) = w;
            }
            if (v1) {
                float2 w = make_float2(acc[mf][nf][2] * EMB_SCALE,
                                       acc[mf][nf][3] * EMB_SCALE);
                *(float2*)(o1 + col) = w;
            }
        }
    }
}

// ---------------- host entry ----------------
extern "C" void kernel_launch(void* const* d_in, const int* in_sizes, int n_in,
                              void* d_out, int out_size) {
    // Map inputs by element count (robust to metadata ordering).
    const int* inp = (const int*)d_in[0];
    const float *emb[4] = {0, 0, 0, 0}, *proj[4] = {0, 0, 0, 0};
    for (int i = 1; i < n_in; i++) {
        long sz = in_sizes[i];
        const float* p = (const float*)d_in[i];
        switch (sz) {
            case 20000L * 1024:  emb[0]  = p; break;
            case 1024L * 1024:   proj[0] = p; break;
            case 20000L * 256:   emb[1]  = p; break;
            case 1024L * 256:    proj[1] = p; break;
            case 160000L * 64:   emb[2]  = p; break;
            case 1024L * 64:     proj[2] = p; break;
            case 67735L * 16:    emb[3]  = p; break;
            case 1024L * 16:     proj[3] = p; break;
            default: break;
        }
    }
    float* out = (float*)d_out;

    reset_kernel<<<1, 32>>>();
    partition_kernel<<<N_TOK_TOTAL / 256, 256>>>(inp);

    // worst-case grid: 128 m-tiles x 16 n-tiles x 4 clusters; early-exit
    dim3 grid(N_TOK_TOTAL / 128, DPROJ / 64, 4);
    fused_gemm_tc<<<grid, 256>>>(emb[0], emb[1], emb[2], emb[3],
                                 proj[0], proj[1], proj[2], proj[3], out);
}

// round 7
// speedup vs baseline: 2.9198x; 1.0919x over previous
#include <cuda_runtime.h>
#include <stdint.h>

#define N_TOK_TOTAL 16384
#define DPROJ 1024
#define EMB_SCALE 32.0f

// ---------------- device scratch (no allocations allowed) ----------------
__device__ int g_count[4];
__device__ int g_list[4][N_TOK_TOTAL];   // flat token index (output row)
__device__ int g_row[4][N_TOK_TOTAL];    // local embedding row

__global__ void reset_kernel() {
    if (threadIdx.x < 4) g_count[threadIdx.x] = 0;
}

__global__ void partition_kernel(const int* __restrict__ inp) {
    int t = blockIdx.x * blockDim.x + threadIdx.x;
    if (t >= N_TOK_TOTAL) return;
    int idx = inp[t];
    int c, l;
    if (idx < 20000)      { c = 0; l = 0; }
    else if (idx < 40000) { c = 1; l = 20000; }
    else if (idx < 200000){ c = 2; l = 40000; }
    else                  { c = 3; l = 200000; }
    int pos = atomicAdd(&g_count[c], 1);
    g_list[c][pos] = t;
    g_row[c][pos]  = idx - l;
}

__device__ __forceinline__ uint32_t f2tf32(float f) {
    uint32_t u;
    asm("cvt.rna.tf32.f32 %0, %1;" : "=r"(u) : "f"(f));
    return u;
}

// ---------------- fused tf32 mma.sync GEMM, double-buffered ----------------
// grid: (m-tile[128], n-tile[64], cluster). Early-exit on dynamic counts.
// D[m, n] = sum_k A[m, k] * B[n, k]; A = gathered emb rows, B = proj rows.
// 8 warps in 4(M) x 2(N) grid; each warp 32x32 via m16n8k8 tf32 frags.
// Pipeline: LDG(ch+1) -> MMA(ch) -> cvt+STS(ch+1, other buffer) -> sync.
__global__ __launch_bounds__(256, 2)
void fused_gemm_tc(const float* __restrict__ e0, const float* __restrict__ e1,
                   const float* __restrict__ e2, const float* __restrict__ e3,
                   const float* __restrict__ p0, const float* __restrict__ p1,
                   const float* __restrict__ p2, const float* __restrict__ p3,
                   float* __restrict__ out)
{
    constexpr int TM = 128, TN = 64;
    constexpr int ST = 36;                    // padded stride (floats); 144B rows
    __shared__ float sA[2][TM * ST];          // 2 x 18.4 KB
    __shared__ float sB[2][TN * ST];          // 2 x  9.2 KB

    const int c = blockIdx.z;
    const int count = g_count[c];
    const int m0 = blockIdx.x * TM;
    if (m0 >= count) return;
    const int n0 = blockIdx.y * TN;

    const float* emb  = (c == 0) ? e0 : (c == 1) ? e1 : (c == 2) ? e2 : e3;
    const float* proj = (c == 0) ? p0 : (c == 1) ? p1 : (c == 2) ? p2 : p3;
    const int K = (c == 0) ? 1024 : (c == 1) ? 256 : (c == 2) ? 64 : 16;
    const int nchunk = (K + 31) >> 5;

    const int tid = threadIdx.x;
    const int wid = tid >> 5;
    const int lid = tid & 31;
    const int wy = wid & 3;          // M warp coord (x32)
    const int wx = wid >> 2;         // N warp coord (x32)
    const int g   = lid >> 2;        // fragment groupID (0..7)
    const int tig = lid & 3;         // thread-in-group (0..3)

    // load-slot geometry: A: 128 rows x 8 float4 over 256 thr -> 4 slots;
    //                     B:  64 rows x 8 float4 over 256 thr -> 2 slots
    const int aM[4] = { (tid + 0) >> 3, (tid + 256) >> 3, (tid + 512) >> 3, (tid + 768) >> 3 };
    const int kqA = tid & 7;
    int arow[4];
#pragma unroll
    for (int j = 0; j < 4; j++)
        arow[j] = (m0 + aM[j] < count) ? g_row[c][m0 + aM[j]] : -1;
    const int bN[2] = { (tid + 0) >> 3, (tid + 256) >> 3 };

    float acc[2][4][4];
#pragma unroll
    for (int mf = 0; mf < 2; mf++)
#pragma unroll
        for (int nf = 0; nf < 4; nf++)
#pragma unroll
            for (int q = 0; q < 4; q++) acc[mf][nf][q] = 0.0f;

    float4 av[4], bv[2];
    // ---- preload chunk 0 into registers
#pragma unroll
    for (int j = 0; j < 4; j++) {
        int kk = kqA * 4;
        av[j] = make_float4(0.f, 0.f, 0.f, 0.f);
        if (arow[j] >= 0 && kk < K)
            av[j] = *(const float4*)(emb + (size_t)arow[j] * K + kk);
    }
#pragma unroll
    for (int j = 0; j < 2; j++) {
        int kk = kqA * 4;
        bv[j] = make_float4(0.f, 0.f, 0.f, 0.f);
        if (kk < K)
            bv[j] = *(const float4*)(proj + (size_t)(n0 + bN[j]) * K + kk);
    }
    // ---- cvt + store chunk 0 into buffer 0
#pragma unroll
    for (int j = 0; j < 4; j++) {
        float* d = &sA[0][aM[j] * ST + kqA * 4];
        d[0] = __uint_as_float(f2tf32(av[j].x));
        d[1] = __uint_as_float(f2tf32(av[j].y));
        d[2] = __uint_as_float(f2tf32(av[j].z));
        d[3] = __uint_as_float(f2tf32(av[j].w));
    }
#pragma unroll
    for (int j = 0; j < 2; j++) {
        float* d = &sB[0][bN[j] * ST + kqA * 4];
        d[0] = __uint_as_float(f2tf32(bv[j].x));
        d[1] = __uint_as_float(f2tf32(bv[j].y));
        d[2] = __uint_as_float(f2tf32(bv[j].z));
        d[3] = __uint_as_float(f2tf32(bv[j].w));
    }
    __syncthreads();

    for (int ch = 0; ch < nchunk; ch++) {
        const int buf = ch & 1;
        const bool more = (ch + 1) < nchunk;

        // ---- issue LDGs for next chunk (latency overlapped with MMA below)
        if (more) {
            const int k0n = (ch + 1) << 5;
#pragma unroll
            for (int j = 0; j < 4; j++) {
                int kk = k0n + kqA * 4;
                av[j] = make_float4(0.f, 0.f, 0.f, 0.f);
                if (arow[j] >= 0 && kk < K)
                    av[j] = *(const float4*)(emb + (size_t)arow[j] * K + kk);
            }
#pragma unroll
            for (int j = 0; j < 2; j++) {
                int kk = k0n + kqA * 4;
                bv[j] = make_float4(0.f, 0.f, 0.f, 0.f);
                if (kk < K)
                    bv[j] = *(const float4*)(proj + (size_t)(n0 + bN[j]) * K + kk);
            }
        }

        // ---- consume current buffer: 4 k-steps of m16n8k8
        const float* cA = sA[buf];
        const float* cB = sB[buf];
#pragma unroll
        for (int ks = 0; ks < 4; ks++) {
            const int kk = ks * 8;
            uint32_t A[2][4], B[4][2];
#pragma unroll
            for (int mf = 0; mf < 2; mf++) {
                const float* ba = &cA[(wy * 32 + mf * 16 + g) * ST + kk + tig];
                A[mf][0] = __float_as_uint(ba[0]);
                A[mf][1] = __float_as_uint(ba[8 * ST]);
                A[mf][2] = __float_as_uint(ba[4]);
                A[mf][3] = __float_as_uint(ba[8 * ST + 4]);
            }
#pragma unroll
            for (int nf = 0; nf < 4; nf++) {
                const float* bb = &cB[(wx * 32 + nf * 8 + g) * ST + kk + tig];
                B[nf][0] = __float_as_uint(bb[0]);
                B[nf][1] = __float_as_uint(bb[4]);
            }
#pragma unroll
            for (int mf = 0; mf < 2; mf++)
#pragma unroll
                for (int nf = 0; nf < 4; nf++) {
                    asm volatile(
                        "mma.sync.aligned.m16n8k8.row.col.f32.tf32.tf32.f32 "
                        "{%0,%1,%2,%3}, {%4,%5,%6,%7}, {%8,%9}, {%0,%1,%2,%3};"
                        : "+f"(acc[mf][nf][0]), "+f"(acc[mf][nf][1]),
                          "+f"(acc[mf][nf][2]), "+f"(acc[mf][nf][3])
                        : "r"(A[mf][0]), "r"(A[mf][1]), "r"(A[mf][2]), "r"(A[mf][3]),
                          "r"(B[nf][0]), "r"(B[nf][1]));
                }
        }

        // ---- cvt + store next chunk into the other buffer
        if (more) {
            const int nb = buf ^ 1;
#pragma unroll
            for (int j = 0; j < 4; j++) {
                float* d = &sA[nb][aM[j] * ST + kqA * 4];
                d[0] = __uint_as_float(f2tf32(av[j].x));
                d[1] = __uint_as_float(f2tf32(av[j].y));
                d[2] = __uint_as_float(f2tf32(av[j].z));
                d[3] = __uint_as_float(f2tf32(av[j].w));
            }
#pragma unroll
            for (int j = 0; j < 2; j++) {
                float* d = &sB[nb][bN[j] * ST + kqA * 4];
                d[0] = __uint_as_float(f2tf32(bv[j].x));
                d[1] = __uint_as_float(f2tf32(bv[j].y));
                d[2] = __uint_as_float(f2tf32(bv[j].z));
                d[3] = __uint_as_float(f2tf32(bv[j].w));
            }
        }
        __syncthreads();
    }

    // ---- epilogue: c0,c1 at (row g, col 2*tig..+1); c2,c3 at row g+8
#pragma unroll
    for (int mf = 0; mf < 2; mf++) {
        int r0 = m0 + wy * 32 + mf * 16 + g;
        int r1 = r0 + 8;
        bool v0 = r0 < count, v1 = r1 < count;
        float* o0 = v0 ? out + (size_t)g_list[c][r0] * DPROJ + n0 : nullptr;
        float* o1 = v1 ? out + (size_t)g_list[c][r1] * DPROJ + n0 : nullptr;
#pragma unroll
        for (int nf = 0; nf < 4; nf++) {
            int col = wx * 32 + nf * 8 + 2 * tig;
            if (v0) {
                float2 w = make_float2(acc[mf][nf][0] * EMB_SCALE,
                                       acc[mf][nf][1] * EMB_SCALE);
                *(float2*)(o0 + col) = w;
            }
            if (v1) {
                float2 w = make_float2(acc[mf][nf][2] * EMB_SCALE,
                                       acc[mf][nf][3] * EMB_SCALE);
                *(float2*)(o1 + col) = w;
            }
        }
    }
}

// ---------------- host entry ----------------
extern "C" void kernel_launch(void* const* d_in, const int* in_sizes, int n_in,
                              void* d_out, int out_size) {
    // Map inputs by element count (robust to metadata ordering).
    const int* inp = (const int*)d_in[0];
    const float *emb[4] = {0, 0, 0, 0}, *proj[4] = {0, 0, 0, 0};
    for (int i = 1; i < n_in; i++) {
        long sz = in_sizes[i];
        const float* p = (const float*)d_in[i];
        switch (sz) {
            case 20000L * 1024:  emb[0]  = p; break;
            case 1024L * 1024:   proj[0] = p; break;
            case 20000L * 256:   emb[1]  = p; break;
            case 1024L * 256:    proj[1] = p; break;
            case 160000L * 64:   emb[2]  = p; break;
            case 1024L * 64:     proj[2] = p; break;
            case 67735L * 16:    emb[3]  = p; break;
            case 1024L * 16:     proj[3] = p; break;
            default: break;
        }
    }
    float* out = (float*)d_out;

    reset_kernel<<<1, 32>>>();
    partition_kernel<<<N_TOK_TOTAL / 256, 256>>>(inp);

    // worst-case grid: 128 m-tiles x 16 n-tiles x 4 clusters; early-exit
    dim3 grid(N_TOK_TOTAL / 128, DPROJ / 64, 4);
    fused_gemm_tc<<<grid, 256>>>(emb[0], emb[1], emb[2], emb[3],
                                 proj[0], proj[1], proj[2], proj[3], out);
}